// round 12
// baseline (speedup 1.0000x reference)
#include <cuda_runtime.h>
#include <cuda_bf16.h>
#include <math.h>

#define N_NODES 100000
#define N_EDGES 1600000
#define C 64
#define MAXL 512            // per-pair-node list (Poisson(16): P(>512)~0)
#define MAXF 1026           // frontier capacity
#define MAXE 8192           // recorded level-2 edges (~560 expected)
#define MAXM 256            // matches per slot (in-degree cap)
#define BMW 3125            // frontbit words (dedup; touched words cleaned)
#define BLW 256             // bloom words (8192 bits, 1 KB)
#define TPB 256
#define EPT 4
#define NB ((N_EDGES / EPT + TPB - 1) / TPB)   // 1563 blocks per scan
#define K3B 148             // K3 grid: one block per SM, co-residency guaranteed

__device__ __forceinline__ unsigned bloom_bit(int v) {
    return ((unsigned)v * 2654435761u) >> 19;      // 13-bit index [0, 8192)
}

// ---------- device state; zero-invariant restored by K3 ----------
__device__ int      g_deg[N_NODES];       // zeroed by K3 (post-barrier) each call
__device__ unsigned g_frontbit[BMW];      // dedup; zero invariant
__device__ unsigned g_bloom[BLW];         // membership filter; zero invariant
__device__ int      g_slot[N_NODES];      // dirty OK; validated via g_frontier
__device__ int      g_listA[MAXL], g_listB[MAXL];
__device__ int      g_cntA, g_cntB, g_nfront, g_ne, g_tick;  // zero invariant
__device__ int      g_frontier[MAXF];
__device__ float    g_wslot[MAXF];        // rsqrt(deg+1) per frontier slot
__device__ int      g_esrc[MAXE], g_eslot[MAXE];
__device__ float    g_h1[MAXF * C];
__device__ unsigned g_barcnt, g_bargen;   // K3 grid barrier state (zero-init)

// ---------- helpers ----------
__device__ __forceinline__ int sniff_is32(const void* edge) {
    const long long* e = (const long long*)edge;
    int is32 = 0;
    #pragma unroll
    for (int k = 0; k < 16; k++) {
        long long v = e[k];
        if (v < 0 || v >= N_NODES) { is32 = 1; break; }
    }
    return is32;
}
__device__ __forceinline__ int src_at(const void* edge, long long ei, int is32) {
    return is32 ? __ldg((const int*)edge + ei)
                : (int)__ldg((const long long*)edge + ei);
}
__device__ __forceinline__ void load_dst4(const void* edge, long long base,
                                          int is32, int d[4]) {
    if (is32) {
        const int* dp = (const int*)edge + N_EDGES;
        int4 t = *(const int4*)(dp + base);
        d[0] = t.x; d[1] = t.y; d[2] = t.z; d[3] = t.w;
    } else {
        const long long* dp = (const long long*)edge + N_EDGES;
        longlong2 a = *(const longlong2*)(dp + base);
        longlong2 b = *(const longlong2*)(dp + base + 2);
        d[0] = (int)a.x; d[1] = (int)a.y; d[2] = (int)b.x; d[3] = (int)b.y;
    }
}
__device__ __forceinline__ void fr_insert(int v) {
    if ((unsigned)v >= N_NODES) return;
    unsigned m = 1u << (v & 31);
    unsigned old = atomicOr(&g_frontbit[v >> 5], m);
    if (!(old & m)) {
        unsigned b = bloom_bit(v);
        atomicOr(&g_bloom[b >> 5], 1u << (b & 31));
        int s = atomicAdd(&g_nfront, 1);
        if (s < MAXF) { g_frontier[s] = v; g_slot[v] = s; }
    }
}

// ---------- K1: scan dst -> degree atomics + pair lists + frontier ----
// (g_deg arrives zeroed: statically at load, then by K3 each call)
__global__ __launch_bounds__(TPB)
void k_scan1(const void* __restrict__ edge, const void* __restrict__ pair) {
    __shared__ int s_is32, s_p0, s_p1;
    if (threadIdx.x == 0) {
        int is32 = sniff_is32(edge);
        s_is32 = is32;
        s_p0 = is32 ? __ldg((const int*)pair)     : (int)__ldg((const long long*)pair);
        s_p1 = is32 ? __ldg((const int*)pair + 1) : (int)__ldg((const long long*)pair + 1);
    }
    __syncthreads();
    const int is32 = s_is32, p0 = s_p0, p1 = s_p1;
    const int gt = blockIdx.x * TPB + threadIdx.x;
    if (gt == 0) { fr_insert(p0); fr_insert(p1); }

    long long base = (long long)gt * EPT;
    if (base >= N_EDGES) return;
    int d[4];
    load_dst4(edge, base, is32, d);
    #pragma unroll
    for (int k = 0; k < EPT; k++) {
        int dd = d[k];
        if ((unsigned)dd >= N_NODES) continue;
        atomicAdd(&g_deg[dd], 1);
        if (dd == p0 || dd == p1) {
            int s = src_at(edge, base + k, is32);
            if ((unsigned)s >= N_NODES) continue;
            if (dd == p0) { int j = atomicAdd(&g_cntA, 1); if (j < MAXL) g_listA[j] = s; }
            if (dd == p1) { int j = atomicAdd(&g_cntB, 1); if (j < MAXL) g_listB[j] = s; }
            fr_insert(s);
        }
    }
}

// ---------- K2: lean scan -> bloom probe + exact validate + record ----
__global__ __launch_bounds__(TPB)
void k_scan2(const void* __restrict__ edge) {
    __shared__ int s_is32;
    __shared__ unsigned s_bl[BLW];                 // 1 KB bloom in SMEM
    if (threadIdx.x == 0) s_is32 = sniff_is32(edge);
    if (threadIdx.x < BLW) s_bl[threadIdx.x] = g_bloom[threadIdx.x];
    __syncthreads();
    const int is32 = s_is32;

    long long base = (blockIdx.x * (long long)TPB + threadIdx.x) * EPT;
    if (base >= N_EDGES) return;
    int d[4];
    load_dst4(edge, base, is32, d);
    #pragma unroll
    for (int k = 0; k < EPT; k++) {
        int dd = d[k];
        if ((unsigned)dd >= N_NODES) continue;
        unsigned b = bloom_bit(dd);
        if ((s_bl[b >> 5] >> (b & 31)) & 1u) {     // ~0.4% of edges pass
            int sl = g_slot[dd];
            if ((unsigned)sl < (unsigned)MAXF && g_frontier[sl] == dd) {  // exact
                int s = src_at(edge, base + k, is32);
                if ((unsigned)s >= N_NODES) continue;
                int j = atomicAdd(&g_ne, 1);
                if (j < MAXE) { g_esrc[j] = s; g_eslot[j] = sl; }
            }
        }
    }
}

// ---------- K3 grid barrier (all K3B blocks co-resident: 1/SM) ----------
__device__ __forceinline__ void gbar_k3() {
    __syncthreads();
    __threadfence();
    if (threadIdx.x == 0) {
        unsigned gen = ((volatile unsigned*)&g_bargen)[0];
        if (atomicAdd(&g_barcnt, 1u) == K3B - 1u) {
            atomicExch(&g_barcnt, 0u);
            __threadfence();
            atomicAdd(&g_bargen, 1u);
        } else {
            while (((volatile unsigned*)&g_bargen)[0] == gen) { __nanosleep(20); }
        }
    }
    __syncthreads();
}

// ---------- K3: layer-1; barrier; zero deg; last block: tail + cleanup ----
__global__ __launch_bounds__(128)
void k_layer1(const void* __restrict__ edge, const void* __restrict__ pair,
              const float* __restrict__ x,
              const float* __restrict__ W1, const float* __restrict__ b1,
              const float* __restrict__ W2, const float* __restrict__ b2,
              const float* __restrict__ fcW, const float* __restrict__ fcb,
              float* __restrict__ out) {
    __shared__ int   s_mu[MAXM];
    __shared__ float s_w[MAXM];
    __shared__ float s_red[2 * C];
    __shared__ int   s_nm, s_last;
    const int tid = threadIdx.x;
    const int c   = tid & (C - 1);
    const int grp = tid >> 6;                 // 0 or 1
    const int nf  = min(g_nfront, MAXF);
    const int ne  = min(g_ne, MAXE);

    // ---- phase A: layer-1 per slot (reads g_deg; stashes slot weights) ----
    for (int s = blockIdx.x; s < nf; s += K3B) {
        if (tid == 0) s_nm = 0;
        __syncthreads();
        for (int j = tid; j < ne; j += 128) {       // wide match collection
            if (g_eslot[j] == s) {
                int m = atomicAdd(&s_nm, 1);
                if (m < MAXM) s_mu[m] = g_esrc[j];
            }
        }
        __syncthreads();
        int nm = min(s_nm, MAXM);
        if (tid < nm) s_w[tid] = rsqrtf((float)(g_deg[s_mu[tid]] + 1));
        __syncthreads();
        float y = 0.0f;
        for (int m = grp; m < nm; m += 2)           // pipelined x gather
            y += s_w[m] * __ldg(&x[(size_t)s_mu[m] * C + c]);
        s_red[tid] = y;
        __syncthreads();
        int v = g_frontier[s];
        float dv = rsqrtf((float)(g_deg[v] + 1));
        if (tid == 0) g_wslot[s] = dv;
        if (grp == 0)
            s_red[c] = dv * (s_red[c] + s_red[C + c])
                     + dv * dv * __ldg(&x[(size_t)v * C + c]);
        __syncthreads();
        if (grp == 0) {
            float acc = __ldg(&b1[c]);
            #pragma unroll
            for (int k = 0; k < C; k++) acc += s_red[k] * __ldg(&W1[k * C + c]);
            g_h1[s * C + c] = fmaxf(acc, 0.0f);
        }
        __syncthreads();
    }

    // ---- phase B: all deg reads done -> cooperative zero of g_deg ----
    gbar_k3();
    {
        const int gt = blockIdx.x * 128 + tid;      // 18944 threads
        int4 z4 = make_int4(0, 0, 0, 0);
        for (int i = gt; i < N_NODES / 4; i += K3B * 128)
            ((int4*)g_deg)[i] = z4;
    }

    // ---- last-block ticket ----
    __syncthreads();
    __threadfence();
    if (tid == 0) s_last = (atomicAdd(&g_tick, 1) == K3B - 1) ? 1 : 0;
    __syncthreads();
    if (!s_last) return;
    __threadfence();

    // ================= tail (lane-parallel; deg-free via g_wslot) =========
    __shared__ int   t_su[2 * MAXL];
    __shared__ float t_w[2 * MAXL];
    __shared__ int   t_cnt[2], t_sv[2];
    __shared__ float t_dv[2];
    {
        int is32 = sniff_is32(edge);
        if (tid < 2) {
            int v = is32 ? __ldg((const int*)pair + tid)
                         : (int)__ldg((const long long*)pair + tid);
            t_sv[tid] = -1; t_dv[tid] = 0.0f; t_cnt[tid] = 0;
            if ((unsigned)v < N_NODES) {
                int sv = g_slot[v];
                int ok = ((unsigned)sv < (unsigned)MAXF && g_frontier[sv] == v);
                t_sv[tid] = ok ? sv : -1;
                t_dv[tid] = ok ? g_wslot[sv] : 0.0f;
                t_cnt[tid] = (tid == 0) ? min(g_cntA, MAXL) : min(g_cntB, MAXL);
            }
        }
        __syncthreads();
        for (int p = 0; p < 2; p++) {               // wide slot/weight prefetch
            int cnt = t_cnt[p];
            const int* list = (p == 0) ? g_listA : g_listB;
            for (int j = tid; j < cnt; j += 128) {
                int u = list[j];
                int su = ((unsigned)u < N_NODES) ? g_slot[u] : -1;
                int ok = ((unsigned)su < (unsigned)MAXF && g_frontier[su] == u);
                t_su[p * MAXL + j] = ok ? su : -1;
                t_w[p * MAXL + j]  = ok ? g_wslot[su] : 0.0f;
            }
        }
    }
    __syncthreads();
    float* sz = (float*)s_mu;                       // reuse shared (256 floats)
    {
        int p = grp;
        float dv = t_dv[p];
        float z = 0.0f;
        int sv = t_sv[p];
        if (sv >= 0) z = dv * dv * __ldcg(&g_h1[sv * C + c]);
        int cnt = t_cnt[p];
        for (int j = 0; j < cnt; j++) {             // independent pipelined loads
            int su = t_su[p * MAXL + j];
            if (su >= 0) z += t_w[p * MAXL + j] * dv * __ldcg(&g_h1[su * C + c]);
        }
        sz[tid] = z;
    }
    __syncthreads();
    {
        float acc = __ldg(&b2[c]);
        #pragma unroll
        for (int k = 0; k < C; k++) acc += sz[grp * C + k] * __ldg(&W2[k * C + c]);
        s_red[tid] = fmaxf(acc, 0.0f) * __ldg(&fcW[tid]);
    }
    __syncthreads();
    for (int st = C; st > 0; st >>= 1) {
        if (tid < st) s_red[tid] += s_red[tid + st];
        __syncthreads();
    }
    if (tid == 0) out[0] = 1.0f / (1.0f + expf(-(s_red[0] + __ldg(&fcb[0]))));

    // ---- cleanup (parallel): restore zero-invariant for next replay ----
    __syncthreads();
    for (int i = tid; i < nf; i += 128) {
        int v = g_frontier[i];
        if ((unsigned)v < N_NODES) {
            g_frontbit[v >> 5] = 0u;
            g_bloom[bloom_bit(v) >> 5] = 0u;
        }
    }
    if (tid == 0) { g_cntA = 0; g_cntB = 0; g_nfront = 0; g_ne = 0; g_tick = 0; }
}

// ---------- launch ----------
extern "C" void kernel_launch(void* const* d_in, const int* in_sizes, int n_in,
                              void* d_out, int out_size) {
    const float* x    = (const float*)d_in[0];
    const void*  edge = d_in[1];
    const void*  pair = d_in[2];
    const float* W1   = (const float*)d_in[3];
    const float* b1   = (const float*)d_in[4];
    const float* W2   = (const float*)d_in[5];
    const float* b2   = (const float*)d_in[6];
    const float* fcW  = (const float*)d_in[7];
    const float* fcb  = (const float*)d_in[8];
    float* out = (float*)d_out;

    k_scan1<<<NB, TPB>>>(edge, pair);
    k_scan2<<<NB, TPB>>>(edge);
    k_layer1<<<K3B, 128>>>(edge, pair, x, W1, b1, W2, b2, fcW, fcb, out);
}

// round 14
// speedup vs baseline: 1.2637x; 1.2637x over previous
#include <cuda_runtime.h>
#include <cuda_bf16.h>
#include <math.h>

#define N_NODES 100000
#define N_EDGES 1600000
#define C 64
#define MAXL 512            // per-pair-node list (Poisson(16): P(>512)~0)
#define MAXF 1026           // frontier capacity
#define MAXE 8192           // recorded level-2 edges (~560 expected)
#define MAXM 256            // matches per slot (in-degree cap)
#define BMW 3125            // frontbit words (dedup; touched words cleaned)
#define BLW 256             // bloom words (8192 bits, 1 KB)
#define EPT 4
#define GRIDB 592           // 4 blocks/SM * 148 SMs -> co-resident by construction
#define TPBM 256

__device__ __forceinline__ unsigned bloom_bit(int v) {
    return ((unsigned)v * 2654435761u) >> 19;      // 13-bit index [0, 8192)
}

// ---------- device state; zero-invariant restored each call ----------
__device__ int      g_deg[N_NODES];       // zeroed in P-A each call
__device__ unsigned g_frontbit[BMW];      // dedup; zero invariant (cleanup)
__device__ unsigned g_bloom[BLW];         // frontier filter; zero invariant
__device__ int      g_slot[N_NODES];      // dirty OK; validated via g_frontier
__device__ int      g_listA[MAXL], g_listB[MAXL];
__device__ int      g_cntA, g_cntB, g_nfront, g_ne, g_tick;  // zero invariant
__device__ int      g_frontier[MAXF];
__device__ float    g_wslot[MAXF];        // rsqrt(deg+1) per frontier slot
__device__ int      g_esrc[MAXE], g_eslot[MAXE];
__device__ float    g_h1[MAXF * C];
__device__ unsigned g_barcnt, g_bargen;   // barrier state (zero static init)

// ---------- helpers ----------
__device__ __forceinline__ int sniff_is32(const void* edge) {
    const long long* e = (const long long*)edge;
    int is32 = 0;
    #pragma unroll
    for (int k = 0; k < 16; k++) {
        long long v = e[k];
        if (v < 0 || v >= N_NODES) { is32 = 1; break; }
    }
    return is32;
}
__device__ __forceinline__ int src_at(const void* edge, long long ei, int is32) {
    return is32 ? __ldg((const int*)edge + ei)
                : (int)__ldg((const long long*)edge + ei);
}
__device__ __forceinline__ void load_dst4(const void* edge, long long base,
                                          int is32, int d[4]) {
    if (is32) {
        const int* dp = (const int*)edge + N_EDGES;
        int4 t = *(const int4*)(dp + base);
        d[0] = t.x; d[1] = t.y; d[2] = t.z; d[3] = t.w;
    } else {
        const long long* dp = (const long long*)edge + N_EDGES;
        longlong2 a = *(const longlong2*)(dp + base);
        longlong2 b = *(const longlong2*)(dp + base + 2);
        d[0] = (int)a.x; d[1] = (int)a.y; d[2] = (int)b.x; d[3] = (int)b.y;
    }
}
__device__ __forceinline__ void fr_insert(int v) {
    if ((unsigned)v >= N_NODES) return;
    unsigned m = 1u << (v & 31);
    unsigned old = atomicOr(&g_frontbit[v >> 5], m);
    if (!(old & m)) {
        unsigned b = bloom_bit(v);
        atomicOr(&g_bloom[b >> 5], 1u << (b & 31));
        int s = atomicAdd(&g_nfront, 1);
        if (s < MAXF) { g_frontier[s] = v; g_slot[v] = s; }
    }
}
// grid barrier: all GRIDB blocks are co-resident (4/SM enforced by launch bounds)
__device__ __forceinline__ void gbar() {
    __syncthreads();
    __threadfence();
    if (threadIdx.x == 0) {
        unsigned gen = ((volatile unsigned*)&g_bargen)[0];
        if (atomicAdd(&g_barcnt, 1u) == GRIDB - 1u) {
            atomicExch(&g_barcnt, 0u);
            __threadfence();
            atomicAdd(&g_bargen, 1u);
        } else {
            while (((volatile unsigned*)&g_bargen)[0] == gen) { __nanosleep(20); }
        }
    }
    __syncthreads();
}

// ---------- the whole pipeline, one launch ----------
__global__ __launch_bounds__(TPBM, 4)
void k_all(const float* __restrict__ x,
           const void*  __restrict__ edge,
           const void*  __restrict__ pair,
           const float* __restrict__ W1, const float* __restrict__ b1,
           const float* __restrict__ W2, const float* __restrict__ b2,
           const float* __restrict__ fcW, const float* __restrict__ fcb,
           float* __restrict__ out) {
    __shared__ unsigned s_bl[BLW];                 // 1 KB bloom copy
    __shared__ int   s_mu[MAXM];
    __shared__ float s_w[MAXM];
    __shared__ float s_red[TPBM];
    __shared__ float u_sz[2 * C];
    __shared__ int   t_su[2 * MAXL];
    __shared__ float t_w2[2 * MAXL];
    __shared__ int   t_cnt[2], t_sv[2];
    __shared__ float t_dv[2];
    __shared__ int   s_nm, s_last, s_is32, s_p0, s_p1;

    const int tid = threadIdx.x;
    const int bid = blockIdx.x;
    const int gt  = bid * TPBM + tid;
    const int nthr = GRIDB * TPBM;

    if (tid == 0) {
        int is32 = sniff_is32(edge);
        s_is32 = is32;
        s_p0 = is32 ? __ldg((const int*)pair)     : (int)__ldg((const long long*)pair);
        s_p1 = is32 ? __ldg((const int*)pair + 1) : (int)__ldg((const long long*)pair + 1);
    }
    __syncthreads();
    const int is32 = s_is32, p0 = s_p0, p1 = s_p1;
    const long long nch = N_EDGES / EPT;           // 400000 4-edge chunks

    // ---- P-A: zero deg + pair scan -> lists + frontier + bloom ----
    {
        int4 z4 = make_int4(0, 0, 0, 0);
        for (int i = gt; i < N_NODES / 4; i += nthr) ((int4*)g_deg)[i] = z4;
        if (gt == 0) { fr_insert(p0); fr_insert(p1); }
        for (long long ch = gt; ch < nch; ch += nthr) {
            long long base = ch * EPT;
            int d[4];
            load_dst4(edge, base, is32, d);
            #pragma unroll
            for (int k = 0; k < EPT; k++) {
                int dd = d[k];
                if (dd == p0 || dd == p1) {
                    int s = src_at(edge, base + k, is32);
                    if ((unsigned)s >= N_NODES) continue;
                    if (dd == p0) { int j = atomicAdd(&g_cntA, 1); if (j < MAXL) g_listA[j] = s; }
                    if (dd == p1) { int j = atomicAdd(&g_cntB, 1); if (j < MAXL) g_listB[j] = s; }
                    fr_insert(s);
                }
            }
        }
    }
    gbar();

    // ---- P-B: deg atomics + bloom probe + exact validate + record ----
    for (int i = tid; i < BLW; i += TPBM) s_bl[i] = g_bloom[i];
    __syncthreads();
    for (long long ch = gt; ch < nch; ch += nthr) {
        long long base = ch * EPT;
        int d[4];
        load_dst4(edge, base, is32, d);
        #pragma unroll
        for (int k = 0; k < EPT; k++) {
            int dd = d[k];
            if ((unsigned)dd >= N_NODES) continue;
            atomicAdd(&g_deg[dd], 1);
            unsigned b = bloom_bit(dd);
            if ((s_bl[b >> 5] >> (b & 31)) & 1u) {
                int sl = g_slot[dd];
                if ((unsigned)sl < (unsigned)MAXF && g_frontier[sl] == dd) {
                    int s = src_at(edge, base + k, is32);
                    if ((unsigned)s >= N_NODES) continue;
                    int j = atomicAdd(&g_ne, 1);
                    if (j < MAXE) { g_esrc[j] = s; g_eslot[j] = sl; }
                }
            }
        }
    }
    gbar();

    // ---- P-C: layer-1 per slot (256 threads = 4 gather groups) ----
    const int nf = min(g_nfront, MAXF);
    const int ne = min(g_ne, MAXE);
    const int c   = tid & (C - 1);
    const int grp = tid >> 6;                      // 0..3
    for (int s = bid; s < nf; s += GRIDB) {
        if (tid == 0) s_nm = 0;
        __syncthreads();
        for (int j = tid; j < ne; j += TPBM) {     // wide match collection
            if (g_eslot[j] == s) {
                int m = atomicAdd(&s_nm, 1);
                if (m < MAXM) s_mu[m] = g_esrc[j];
            }
        }
        __syncthreads();
        int nm = min(s_nm, MAXM);
        if (tid < nm) s_w[tid] = rsqrtf((float)(g_deg[s_mu[tid]] + 1));
        __syncthreads();
        float y = 0.0f;
        for (int m = grp; m < nm; m += 4)          // pipelined x gather
            y += s_w[m] * __ldg(&x[(size_t)s_mu[m] * C + c]);
        s_red[tid] = y;
        __syncthreads();
        int v = g_frontier[s];
        float dv = rsqrtf((float)(g_deg[v] + 1));
        if (tid == 0) g_wslot[s] = dv;
        if (grp == 0)
            s_red[c] = dv * (s_red[c] + s_red[C + c] + s_red[2 * C + c] + s_red[3 * C + c])
                     + dv * dv * __ldg(&x[(size_t)v * C + c]);
        __syncthreads();
        if (grp == 0) {
            float acc = __ldg(&b1[c]);
            #pragma unroll
            for (int k = 0; k < C; k++) acc += s_red[k] * __ldg(&W1[k * C + c]);
            g_h1[s * C + c] = fmaxf(acc, 0.0f);
        }
        __syncthreads();
    }

    // ---- last-block ticket ----
    __threadfence();
    if (tid == 0) s_last = (atomicAdd(&g_tick, 1) == GRIDB - 1) ? 1 : 0;
    __syncthreads();
    if (!s_last) return;
    __threadfence();

    // ================= tail (lane-parallel; weights via g_wslot) ==========
    if (tid < 2) {
        int v = (tid == 0) ? p0 : p1;
        t_sv[tid] = -1; t_dv[tid] = 0.0f; t_cnt[tid] = 0;
        if ((unsigned)v < N_NODES) {
            int sv = g_slot[v];
            int ok = ((unsigned)sv < (unsigned)MAXF && g_frontier[sv] == v);
            t_sv[tid] = ok ? sv : -1;
            t_dv[tid] = ok ? g_wslot[sv] : 0.0f;
            t_cnt[tid] = (tid == 0) ? min(g_cntA, MAXL) : min(g_cntB, MAXL);
        }
    }
    __syncthreads();
    for (int p = 0; p < 2; p++) {                  // wide slot/weight prefetch
        int cnt = t_cnt[p];
        const int* list = (p == 0) ? g_listA : g_listB;
        for (int j = tid; j < cnt; j += TPBM) {
            int u = list[j];
            int su = ((unsigned)u < N_NODES) ? g_slot[u] : -1;
            int ok = ((unsigned)su < (unsigned)MAXF && g_frontier[su] == u);
            t_su[p * MAXL + j] = ok ? su : -1;
            t_w2[p * MAXL + j] = ok ? g_wslot[su] : 0.0f;
        }
    }
    __syncthreads();
    if (tid < 2 * C) {
        int p = tid >> 6;
        float dv = t_dv[p];
        float z = 0.0f;
        int sv = t_sv[p];
        if (sv >= 0) z = dv * dv * __ldcg(&g_h1[sv * C + c]);
        int cnt = t_cnt[p];
        for (int j = 0; j < cnt; j++) {            // independent pipelined loads
            int su = t_su[p * MAXL + j];
            if (su >= 0) z += t_w2[p * MAXL + j] * dv * __ldcg(&g_h1[su * C + c]);
        }
        u_sz[tid] = z;
    }
    __syncthreads();
    if (tid < 2 * C) {
        int p = tid >> 6;
        float acc = __ldg(&b2[c]);
        #pragma unroll
        for (int k = 0; k < C; k++) acc += u_sz[p * C + k] * __ldg(&W2[k * C + c]);
        s_red[tid] = fmaxf(acc, 0.0f) * __ldg(&fcW[tid]);
    }
    __syncthreads();
    for (int st = C; st > 0; st >>= 1) {
        if (tid < st) s_red[tid] += s_red[tid + st];
        __syncthreads();
    }
    if (tid == 0) out[0] = 1.0f / (1.0f + expf(-(s_red[0] + __ldg(&fcb[0]))));

    // ---- cleanup (parallel): restore zero-invariant for next replay ----
    __syncthreads();
    for (int i = tid; i < nf; i += TPBM) {
        int v = g_frontier[i];
        if ((unsigned)v < N_NODES) {
            g_frontbit[v >> 5] = 0u;
            g_bloom[bloom_bit(v) >> 5] = 0u;
        }
    }
    if (tid == 0) { g_cntA = 0; g_cntB = 0; g_nfront = 0; g_ne = 0; g_tick = 0; }
}

// ---------- launch ----------
extern "C" void kernel_launch(void* const* d_in, const int* in_sizes, int n_in,
                              void* d_out, int out_size) {
    const float* x    = (const float*)d_in[0];
    const void*  edge = d_in[1];
    const void*  pair = d_in[2];
    const float* W1   = (const float*)d_in[3];
    const float* b1   = (const float*)d_in[4];
    const float* W2   = (const float*)d_in[5];
    const float* b2   = (const float*)d_in[6];
    const float* fcW  = (const float*)d_in[7];
    const float* fcb  = (const float*)d_in[8];
    float* out = (float*)d_out;

    k_all<<<GRIDB, TPBM>>>(x, edge, pair, W1, b1, W2, b2, fcW, fcb, out);
}